// round 3
// baseline (speedup 1.0000x reference)
#include <cuda_runtime.h>

// saivrNet: out = W_out * sigmoid^{10 layers}(W_h * (W_in x + b_in) ...) + b_out
// Strategy:
//  - work in g = tanh space: sigmoid(u) = 0.5 + 0.5*tanh(u/2); fold the affine
//    0.5+0.5g into the NEXT layer's weights so each sigmoid = 1 MUFU.TANH.
//  - layers 1..9 use tanh.approx (abs err ~5e-4, contracted by ~0.375/layer),
//    layer 10 uses accurate EX2+RCP tanh so the surviving error is ~1e-4.
//  - fma.rn.f32x2 packed fp32 (sm_100+) processes 2 adjacent rows per thread
//    at 2x FFMA rate, full fp32 precision; outputs store as STG.64.
//  - tiny fold kernel precomputes A = 0.5*Wh*Win etc. into __device__ memory;
//    main kernel amortizes weight loads over 16 rows/thread.

typedef unsigned long long u64;

__device__ float g_fold[64];
// layout: A[3][8] @0..23 (layer-1 tanh arg = A*x + D)
//         D[3]    @24..26
//         W2[3][3]@27..35 (= 0.25*W_h), C2[3] @36..38 (= 0.5*b_h + 0.25*rowsum(W_h))
//         WO[5][3]@39..53 (= 0.5*W_out), CO[5] @54..58 (= b_out + 0.5*rowsum(W_out))

__device__ __forceinline__ float tanh_ap(float x) {
    float y; asm("tanh.approx.f32 %0, %1;" : "=f"(y) : "f"(x)); return y;
}
__device__ __forceinline__ float ex2_ap(float x) {
    float y; asm("ex2.approx.f32 %0, %1;" : "=f"(y) : "f"(x)); return y;
}
__device__ __forceinline__ float rcp_ap(float x) {
    float y; asm("rcp.approx.f32 %0, %1;" : "=f"(y) : "f"(x)); return y;
}
// accurate tanh: tanh(a) = (1 - e)/(1 + e), e = 2^(-2*log2(e)*a)
__device__ __forceinline__ float tanh_acc(float a) {
    float e = ex2_ap(-2.8853900817779268f * a);
    return (1.0f - e) * rcp_ap(1.0f + e);
}

__device__ __forceinline__ u64 pk2(float lo, float hi) {
    u64 r; asm("mov.b64 %0, {%1, %2};" : "=l"(r) : "f"(lo), "f"(hi)); return r;
}
__device__ __forceinline__ void upk2(u64 v, float& lo, float& hi) {
    asm("mov.b64 {%0, %1}, %2;" : "=f"(lo), "=f"(hi) : "l"(v));
}
__device__ __forceinline__ u64 dup2(float w) { return pk2(w, w); }
// packed fp32 FMA: d = a*b + c per 32-bit lane (sm_100+)
__device__ __forceinline__ u64 fma2(u64 a, u64 b, u64 c) {
    u64 d; asm("fma.rn.f32x2 %0, %1, %2, %3;" : "=l"(d) : "l"(a), "l"(b), "l"(c));
    return d;
}

// ---------------------------------------------------------------------------
// Fold kernel: 1 thread, negligible cost, precomputes all derived weights.
// ---------------------------------------------------------------------------
__global__ void fold_kernel(const float* __restrict__ Win, const float* __restrict__ bin,
                            const float* __restrict__ Wh,  const float* __restrict__ bh,
                            const float* __restrict__ Wout, const float* __restrict__ bout) {
    if (threadIdx.x != 0 || blockIdx.x != 0) return;
    for (int r = 0; r < 3; r++) {
        for (int c = 0; c < 8; c++) {
            float a = 0.f;
            for (int k = 0; k < 3; k++) a += Wh[r * 3 + k] * Win[k * 8 + c];
            g_fold[r * 8 + c] = 0.5f * a;
        }
        float dd = bh[r];
        for (int k = 0; k < 3; k++) dd += Wh[r * 3 + k] * bin[k];
        g_fold[24 + r] = 0.5f * dd;
        float s = 0.f;
        for (int k = 0; k < 3; k++) { g_fold[27 + r * 3 + k] = 0.25f * Wh[r * 3 + k]; s += Wh[r * 3 + k]; }
        g_fold[36 + r] = 0.5f * bh[r] + 0.25f * s;
    }
    for (int c = 0; c < 5; c++) {
        float s = 0.f;
        for (int r = 0; r < 3; r++) { g_fold[39 + c * 3 + r] = 0.5f * Wout[c * 3 + r]; s += Wout[c * 3 + r]; }
        g_fold[54 + c] = bout[c] + 0.5f * s;
    }
}

// ---------------------------------------------------------------------------
// Main kernel: each thread handles PPT pairs of adjacent rows (16 rows).
// ---------------------------------------------------------------------------
#define TPB 128
#define PPT 8

__device__ __forceinline__ float dot8(const float* A, int r, float4 v0, float4 v1, float bias) {
    float t = bias;
    t = fmaf(A[r * 8 + 0], v0.x, t);
    t = fmaf(A[r * 8 + 1], v0.y, t);
    t = fmaf(A[r * 8 + 2], v0.z, t);
    t = fmaf(A[r * 8 + 3], v0.w, t);
    t = fmaf(A[r * 8 + 4], v1.x, t);
    t = fmaf(A[r * 8 + 5], v1.y, t);
    t = fmaf(A[r * 8 + 6], v1.z, t);
    t = fmaf(A[r * 8 + 7], v1.w, t);
    return t;
}

__global__ __launch_bounds__(TPB, 4)
void mlp_main(const float4* __restrict__ x4, float* __restrict__ out, int N) {
    // Load folded weights into registers (uniform LDG, L1-cached, amortized over 16 rows)
    float A[24];
#pragma unroll
    for (int i = 0; i < 24; i++) A[i] = g_fold[i];
    const float D0 = g_fold[24], D1 = g_fold[25], D2 = g_fold[26];
    u64 W2p[9], C2p[3], WOp[15], COp[5];
#pragma unroll
    for (int i = 0; i < 9; i++)  W2p[i] = dup2(g_fold[27 + i]);
#pragma unroll
    for (int i = 0; i < 3; i++)  C2p[i] = dup2(g_fold[36 + i]);
#pragma unroll
    for (int i = 0; i < 15; i++) WOp[i] = dup2(g_fold[39 + i]);
#pragma unroll
    for (int i = 0; i < 5; i++)  COp[i] = dup2(g_fold[54 + i]);

    const int nPairs = N >> 1;
    const int stride = gridDim.x * TPB;
    int p = blockIdx.x * TPB + threadIdx.x;

#pragma unroll
    for (int it = 0; it < PPT; ++it, p += stride) {
        if (p >= nPairs) break;
        const size_t base = (size_t)p * 4;
        const float4 a0 = x4[base + 0], a1 = x4[base + 1];   // row 2p
        const float4 b0 = x4[base + 2], b1 = x4[base + 3];   // row 2p+1

        // layer 1: tanh arg = A*x + D  (scalar per row), then pack g-pairs
        u64 g0, g1, g2;
        {
            float u00 = dot8(A, 0, a0, a1, D0), u01 = dot8(A, 0, b0, b1, D0);
            float u10 = dot8(A, 1, a0, a1, D1), u11 = dot8(A, 1, b0, b1, D1);
            float u20 = dot8(A, 2, a0, a1, D2), u21 = dot8(A, 2, b0, b1, D2);
            g0 = pk2(tanh_ap(u00), tanh_ap(u01));
            g1 = pk2(tanh_ap(u10), tanh_ap(u11));
            g2 = pk2(tanh_ap(u20), tanh_ap(u21));
        }

        // layers 2..9 (8 iterations), packed f32x2 matmul + approx tanh
#pragma unroll
        for (int l = 0; l < 8; l++) {
            u64 q0 = fma2(W2p[0], g0, fma2(W2p[1], g1, fma2(W2p[2], g2, C2p[0])));
            u64 q1 = fma2(W2p[3], g0, fma2(W2p[4], g1, fma2(W2p[5], g2, C2p[1])));
            u64 q2 = fma2(W2p[6], g0, fma2(W2p[7], g1, fma2(W2p[8], g2, C2p[2])));
            float lo, hi;
            upk2(q0, lo, hi); g0 = pk2(tanh_ap(lo), tanh_ap(hi));
            upk2(q1, lo, hi); g1 = pk2(tanh_ap(lo), tanh_ap(hi));
            upk2(q2, lo, hi); g2 = pk2(tanh_ap(lo), tanh_ap(hi));
        }

        // layer 10: accurate tanh (dominant error term)
        {
            u64 q0 = fma2(W2p[0], g0, fma2(W2p[1], g1, fma2(W2p[2], g2, C2p[0])));
            u64 q1 = fma2(W2p[3], g0, fma2(W2p[4], g1, fma2(W2p[5], g2, C2p[1])));
            u64 q2 = fma2(W2p[6], g0, fma2(W2p[7], g1, fma2(W2p[8], g2, C2p[2])));
            float lo, hi;
            upk2(q0, lo, hi); g0 = pk2(tanh_acc(lo), tanh_acc(hi));
            upk2(q1, lo, hi); g1 = pk2(tanh_acc(lo), tanh_acc(hi));
            upk2(q2, lo, hi); g2 = pk2(tanh_acc(lo), tanh_acc(hi));
        }

        // output layer: packed result = two adjacent rows' column c -> STG.64
#pragma unroll
        for (int c = 0; c < 5; c++) {
            u64 o = fma2(WOp[c * 3 + 0], g0, fma2(WOp[c * 3 + 1], g1, fma2(WOp[c * 3 + 2], g2, COp[c])));
            reinterpret_cast<u64*>(out + (size_t)c * N)[p] = o;
        }
    }
}

// Handles the last row if N is odd (not the case for this dataset, but safe).
__global__ void tail_kernel(const float* __restrict__ x, float* __restrict__ out, int N) {
    if (threadIdx.x != 0 || blockIdx.x != 0) return;
    int r = N - 1;
    const float* xr = x + (size_t)r * 8;
    float g[3];
    for (int u = 0; u < 3; u++) {
        float t = g_fold[24 + u];
        for (int c = 0; c < 8; c++) t = fmaf(g_fold[u * 8 + c], xr[c], t);
        g[u] = tanh_acc(t);
    }
    for (int l = 0; l < 9; l++) {
        float q[3];
        for (int u = 0; u < 3; u++) {
            float t = g_fold[36 + u];
            for (int k = 0; k < 3; k++) t = fmaf(g_fold[27 + u * 3 + k], g[k], t);
            q[u] = t;
        }
        for (int u = 0; u < 3; u++) g[u] = tanh_acc(q[u]);
    }
    for (int c = 0; c < 5; c++) {
        float t = g_fold[54 + c];
        for (int u = 0; u < 3; u++) t = fmaf(g_fold[39 + c * 3 + u], g[u], t);
        out[(size_t)c * N + r] = t;
    }
}

extern "C" void kernel_launch(void* const* d_in, const int* in_sizes, int n_in,
                              void* d_out, int out_size) {
    const float* x    = (const float*)d_in[0];
    const float* Win  = (const float*)d_in[1];
    const float* bin  = (const float*)d_in[2];
    const float* Wh   = (const float*)d_in[3];
    const float* bh   = (const float*)d_in[4];
    const float* Wout = (const float*)d_in[5];
    const float* bout = (const float*)d_in[6];
    float* out = (float*)d_out;

    const int N = in_sizes[0] / 8;

    fold_kernel<<<1, 32>>>(Win, bin, Wh, bh, Wout, bout);

    const int nPairs = N >> 1;
    const int threads = (nPairs + PPT - 1) / PPT;
    const int blocks = (threads + TPB - 1) / TPB;
    if (blocks > 0)
        mlp_main<<<blocks, TPB>>>((const float4*)x, out, N);
    if (N & 1)
        tail_kernel<<<1, 32>>>(x, out, N);
}